// round 1
// baseline (speedup 1.0000x reference)
#include <cuda_runtime.h>

#define Cn 16
#define Hn 512
#define Wn 512
#define HWn (Hn*Wn)
#define HIDn 128
#define KFn 80          // 5*C gathered features
#define BXn 128         // pixels per block (one row segment)
#define ROWSTRIDE 132   // 130 used (halo) + pad

// dynamic smem layout (floats)
#define OFF_W1   0
#define OFF_B1   10240
#define OFF_W2   10368
#define OFF_B2   12416
#define OFF_ROWS 12432
#define SMEM_FLOATS (OFF_ROWS + Cn*3*ROWSTRIDE)   // 18768 floats = 75072 B

__device__ float g_bufA[Cn*HWn];
__device__ float g_bufB[Cn*HWn];

__global__ void __launch_bounds__(BXn, 2)
slime_step(const float* __restrict__ src, float* __restrict__ dst,
           const float* __restrict__ gW1, const float* __restrict__ gb1,
           const float* __restrict__ gW2, const float* __restrict__ gb2)
{
    extern __shared__ float smem[];
    float* W1s  = smem + OFF_W1;    // [80][128]
    float* b1s  = smem + OFF_B1;    // [128]
    float* W2s  = smem + OFF_W2;    // [128][16]
    float* b2s  = smem + OFF_B2;    // [16]
    float* rows = smem + OFF_ROWS;  // [16][3][ROWSTRIDE], cols 0..129 valid

    const int tid = threadIdx.x;
    const int x0  = blockIdx.x * BXn;
    const int y   = blockIdx.y;

    // ---- cooperative weight/bias loads ----
    {
        const float4* s4 = (const float4*)gW1;
        float4* d4 = (float4*)W1s;
        #pragma unroll
        for (int i = 0; i < (KFn*HIDn/4)/BXn; i++)     // 20 iters
            d4[i*BXn + tid] = s4[i*BXn + tid];
    }
    {
        const float4* s4 = (const float4*)gW2;
        float4* d4 = (float4*)W2s;
        #pragma unroll
        for (int i = 0; i < (HIDn*16/4)/BXn; i++)      // 4 iters
            d4[i*BXn + tid] = s4[i*BXn + tid];
    }
    b1s[tid] = gb1[tid];
    if (tid < 16) b2s[tid] = gb2[tid];

    // ---- stage 3 state rows (with halo) for all 16 channels ----
    const int ym = (y == 0)    ? 0 : (y - 1);     // clamp low edge
    const int yp = (y == Hn-1) ? 0 : (y + 1);     // WRAP at high edge
    for (int i = tid; i < Cn*3*130; i += BXn) {
        int j  = i % 130;          // halo col: gx = x0-1+j
        int t  = i / 130;
        int ri = t % 3;            // 0=up row, 1=center row, 2=down row
        int c  = t / 3;
        int gy = (ri == 0) ? ym : ((ri == 1) ? y : yp);
        int gx = x0 - 1 + j;
        gx = (gx < 0)   ? 0 : gx;  // clamp low edge (left neighbor of x=0 is 0)
        gx = (gx >= Wn) ? 0 : gx;  // WRAP at high edge (right neighbor of x=511 is 0)
        rows[(c*3 + ri)*ROWSTRIDE + j] = src[c*HWn + gy*Wn + gx];
    }
    __syncthreads();

    // ---- gather 80 features into registers ----
    // feature order k = d*16 + c, d in {center, up, down, left, right}
    float f[KFn];
    #pragma unroll
    for (int c = 0; c < Cn; c++) {
        const float* rc = rows + c*3*ROWSTRIDE;
        f[0*Cn+c] = rc[1*ROWSTRIDE + 1 + tid];   // center
        f[1*Cn+c] = rc[0*ROWSTRIDE + 1 + tid];   // up
        f[2*Cn+c] = rc[2*ROWSTRIDE + 1 + tid];   // down
        f[3*Cn+c] = rc[1*ROWSTRIDE + 0 + tid];   // left
        f[4*Cn+c] = rc[1*ROWSTRIDE + 2 + tid];   // right
    }

    float dacc[16];
    #pragma unroll
    for (int o = 0; o < 16; o++) dacc[o] = b2s[o];

    // ---- MLP: hidden in 8 chunks of 16, fuse layer-2 accumulation ----
    #pragma unroll 1
    for (int chunk = 0; chunk < HIDn/16; chunk++) {
        float h[16];
        const float* b1c = b1s + chunk*16;
        #pragma unroll
        for (int j = 0; j < 16; j++) h[j] = b1c[j];

        const float* w1base = W1s + chunk*16;
        #pragma unroll
        for (int k = 0; k < KFn; k++) {          // fully unrolled: f[k] static
            const float fv = f[k];
            const float4* wr = (const float4*)(w1base + k*HIDn);
            #pragma unroll
            for (int q = 0; q < 4; q++) {
                float4 w = wr[q];
                h[q*4+0] = fmaf(fv, w.x, h[q*4+0]);
                h[q*4+1] = fmaf(fv, w.y, h[q*4+1]);
                h[q*4+2] = fmaf(fv, w.z, h[q*4+2]);
                h[q*4+3] = fmaf(fv, w.w, h[q*4+3]);
            }
        }

        const float* w2base = W2s + chunk*16*16;
        #pragma unroll
        for (int j = 0; j < 16; j++) {
            const float hv = fmaxf(h[j], 0.0f);
            const float4* wr = (const float4*)(w2base + j*16);
            #pragma unroll
            for (int q = 0; q < 4; q++) {
                float4 w = wr[q];
                dacc[q*4+0] = fmaf(hv, w.x, dacc[q*4+0]);
                dacc[q*4+1] = fmaf(hv, w.y, dacc[q*4+1]);
                dacc[q*4+2] = fmaf(hv, w.z, dacc[q*4+2]);
                dacc[q*4+3] = fmaf(hv, w.w, dacc[q*4+3]);
            }
        }
    }

    // ---- write: channel 0 is snapshot-restored (constant), others s + delta ----
    const int pix = y*Wn + x0 + tid;
    dst[pix] = f[0];
    #pragma unroll
    for (int c = 1; c < Cn; c++)
        dst[c*HWn + pix] = f[c] + dacc[c];
}

extern "C" void kernel_launch(void* const* d_in, const int* in_sizes, int n_in,
                              void* d_out, int out_size)
{
    const float* state = (const float*)d_in[0];
    const float* W1    = (const float*)d_in[1];
    const float* b1    = (const float*)d_in[2];
    const float* W2    = (const float*)d_in[3];
    const float* b2    = (const float*)d_in[4];
    float* out = (float*)d_out;

    cudaFuncSetAttribute(slime_step,
                         cudaFuncAttributeMaxDynamicSharedMemorySize,
                         SMEM_FLOATS * (int)sizeof(float));

    float *bufA, *bufB;
    cudaGetSymbolAddress((void**)&bufA, g_bufA);
    cudaGetSymbolAddress((void**)&bufB, g_bufB);

    dim3 grid(Wn/BXn, Hn);
    dim3 block(BXn);
    size_t shmem = SMEM_FLOATS * sizeof(float);

    const int n_steps = 8;   // dataset constant (N_STEPS)
    const float* cur = state;
    for (int s = 0; s < n_steps; s++) {
        float* dst = (s == n_steps-1) ? out
                   : ((s % 2 == 0) ? bufA : bufB);
        slime_step<<<grid, block, shmem>>>(cur, dst, W1, b1, W2, b2);
        cur = dst;
    }
}

// round 5
// speedup vs baseline: 1.3343x; 1.3343x over previous
#include <cuda_runtime.h>
#include <cstdint>

#define Cn 16
#define Hn 512
#define Wn 512
#define HWn (Hn*Wn)
#define NSTEPS 8
#define GRIDX 152
#define NTHREADS 256
#define NTILES 2048
#define RS  132     // rows buffer stride (floats)
#define W1S 84      // W1 [n][k] stride
#define W2S 132     // W2 [n][k] stride
#define HS  132     // H  [px][hid] stride

// ---- smem offsets (floats) ----
#define OFF_W1H 0
#define OFF_W1L (OFF_W1H + 128*W1S)      // 10752
#define OFF_W2H (OFF_W1L + 128*W1S)      // 21504
#define OFF_W2L (OFF_W2H + 16*W2S)       // 23616
#define OFF_B1  (OFF_W2L + 16*W2S)       // 25728
#define OFF_B2  (OFF_B1 + 128)           // 25856
#define OFF_ROWS (OFF_B2 + 16)           // 25872
#define OFF_H   (OFF_ROWS + Cn*3*RS)     // 32208
#define SMEM_FLOATS (OFF_H + 128*HS)     // 49104 floats = 196416 B

__device__ float g_bufA[Cn*HWn];
__device__ float g_bufB[Cn*HWn];
__device__ float g_w1h[128*W1S];
__device__ float g_w1l[128*W1S];
__device__ float g_w2h[16*W2S];
__device__ float g_w2l[16*W2S];

__device__ __forceinline__ uint32_t tf32h(float x) {
    uint32_t u;
    asm("cvt.rna.tf32.f32 %0, %1;" : "=r"(u) : "f"(x));
    return u;
}

__device__ __forceinline__ void mma8(float* d,
    uint32_t a0, uint32_t a1, uint32_t a2, uint32_t a3,
    uint32_t b0, uint32_t b1)
{
    asm volatile(
        "mma.sync.aligned.m16n8k8.row.col.f32.tf32.tf32.f32 "
        "{%0,%1,%2,%3}, {%4,%5,%6,%7}, {%8,%9}, {%0,%1,%2,%3};"
        : "+f"(d[0]), "+f"(d[1]), "+f"(d[2]), "+f"(d[3])
        : "r"(a0), "r"(a1), "r"(a2), "r"(a3), "r"(b0), "r"(b1));
}

// ---- weight pre-split + relayout (deterministic, runs every launch) ----
__global__ void w_setup(const float* __restrict__ W1, const float* __restrict__ W2) {
    int t = threadIdx.x;
    for (int i = t; i < 80*128; i += 256) {        // W1[k][n] row-major
        int k = i >> 7, n = i & 127;
        float v = W1[i];
        float hi = __uint_as_float(tf32h(v));
        g_w1h[n*W1S + k] = hi;
        g_w1l[n*W1S + k] = v - hi;
    }
    for (int i = t; i < 128*16; i += 256) {        // W2[k][n]
        int k = i >> 4, n = i & 15;
        float v = W2[i];
        float hi = __uint_as_float(tf32h(v));
        g_w2h[n*W2S + k] = hi;
        g_w2l[n*W2S + k] = v - hi;
    }
}

__global__ void __launch_bounds__(NTHREADS, 1)
slime_step_mma(const float* __restrict__ src, float* __restrict__ dst,
               const float* __restrict__ gb1, const float* __restrict__ gb2)
{
    extern __shared__ float sm[];
    const int tid = threadIdx.x;
    const int w = tid >> 5, lane = tid & 31;
    const int gr = lane >> 2, q = lane & 3;

    // ---- prologue: copy pre-split weights + biases to SMEM ----
    {
        float4* d; const float4* s;
        d = (float4*)(sm + OFF_W1H); s = (const float4*)g_w1h;
        for (int i = tid; i < 128*W1S/4; i += NTHREADS) d[i] = s[i];
        d = (float4*)(sm + OFF_W1L); s = (const float4*)g_w1l;
        for (int i = tid; i < 128*W1S/4; i += NTHREADS) d[i] = s[i];
        d = (float4*)(sm + OFF_W2H); s = (const float4*)g_w2h;
        for (int i = tid; i < 16*W2S/4; i += NTHREADS) d[i] = s[i];
        d = (float4*)(sm + OFF_W2L); s = (const float4*)g_w2l;
        for (int i = tid; i < 16*W2S/4; i += NTHREADS) d[i] = s[i];
        if (tid < 128) sm[OFF_B1 + tid] = gb1[tid];
        if (tid < 16)  sm[OFF_B2 + tid] = gb2[tid];
    }

    // ---- per-thread A-fragment address bases for GEMM1 (tile-invariant) ----
    // feature k = kc*8 + q + 4*s2 ; k = d*16 + c ; d: 0=ctr,1=up,2=down,3=left,4=right
    int foA[20];
    #pragma unroll
    for (int kc = 0; kc < 10; kc++)
        #pragma unroll
        for (int s2 = 0; s2 < 2; s2++) {
            int k = kc*8 + q + 4*s2;
            int dd = k >> 4, c = k & 15;
            int ri = (dd == 1) ? 0 : ((dd == 2) ? 2 : 1);
            int dx = (dd == 3) ? -1 : ((dd == 4) ? 1 : 0);
            foA[kc*2 + s2] = OFF_ROWS + (c*3 + ri)*RS + 1 + dx;
        }

    const int mh = w >> 2, nq = w & 3;
    const int R0 = mh*64, C0 = nq*32;    // GEMM1 warp tile: rows [R0,R0+64), cols [C0,C0+32)
    const int R2 = w*16;                  // GEMM2 warp tile: rows [R2,R2+16), cols [0,16)
    const float* W1hp = sm + OFF_W1H;
    const float* W1lp = sm + OFF_W1L;
    const float* W2hp = sm + OFF_W2H;
    const float* W2lp = sm + OFF_W2L;
    const float* b1s  = sm + OFF_B1;
    const float* b2s  = sm + OFF_B2;
    float* Hs   = sm + OFF_H;
    float* rows = sm + OFF_ROWS;

    for (int t = blockIdx.x; t < NTILES; t += GRIDX) {
        const int y = t >> 2, x0 = (t & 3) << 7;
        __syncthreads();   // previous tile fully consumed (rows + H reuse)

        // ---- stage 3 halo rows for all 16 channels ----
        {
            const int ym = (y == 0)    ? 0 : (y - 1);
            const int yp = (y == Hn-1) ? 0 : (y + 1);
            for (int i = tid; i < Cn*3*130; i += NTHREADS) {
                int j  = i % 130;
                int tt = i / 130;
                int ri = tt % 3, c = tt / 3;
                int gy = (ri == 0) ? ym : ((ri == 1) ? y : yp);
                int gx = x0 - 1 + j;
                gx = (gx < 0)   ? 0 : gx;     // clamp low edge
                gx = (gx >= Wn) ? 0 : gx;     // wrap high edge
                rows[(c*3 + ri)*RS + j] = src[c*HWn + gy*Wn + gx];
            }
        }
        __syncthreads();

        // ================= GEMM1: D1 = X @ W1 (+b1), 3xtf32 =================
        float acc[4][4][4];
        #pragma unroll
        for (int nt = 0; nt < 4; nt++) {
            float bz0 = b1s[C0 + nt*8 + 2*q];
            float bz1 = b1s[C0 + nt*8 + 2*q + 1];
            #pragma unroll
            for (int mt = 0; mt < 4; mt++) {
                acc[mt][nt][0] = bz0; acc[mt][nt][1] = bz1;
                acc[mt][nt][2] = bz0; acc[mt][nt][3] = bz1;
            }
        }
        #pragma unroll
        for (int kc = 0; kc < 10; kc++) {
            uint32_t ah[4][4], al[4][4];
            #pragma unroll
            for (int mt = 0; mt < 4; mt++) {
                int r = R0 + mt*16 + gr;
                float v0 = sm[foA[kc*2+0] + r];
                float v1 = sm[foA[kc*2+0] + r + 8];
                float v2 = sm[foA[kc*2+1] + r];
                float v3 = sm[foA[kc*2+1] + r + 8];
                ah[mt][0] = tf32h(v0); al[mt][0] = __float_as_uint(v0 - __uint_as_float(ah[mt][0]));
                ah[mt][1] = tf32h(v1); al[mt][1] = __float_as_uint(v1 - __uint_as_float(ah[mt][1]));
                ah[mt][2] = tf32h(v2); al[mt][2] = __float_as_uint(v2 - __uint_as_float(ah[mt][2]));
                ah[mt][3] = tf32h(v3); al[mt][3] = __float_as_uint(v3 - __uint_as_float(ah[mt][3]));
            }
            #pragma unroll
            for (int nt = 0; nt < 4; nt++) {
                int n = C0 + nt*8 + gr;
                uint32_t bh0 = __float_as_uint(W1hp[n*W1S + kc*8 + q]);
                uint32_t bh1 = __float_as_uint(W1hp[n*W1S + kc*8 + q + 4]);
                uint32_t bl0 = __float_as_uint(W1lp[n*W1S + kc*8 + q]);
                uint32_t bl1 = __float_as_uint(W1lp[n*W1S + kc*8 + q + 4]);
                #pragma unroll
                for (int mt = 0; mt < 4; mt++) {
                    mma8(acc[mt][nt], ah[mt][0], ah[mt][1], ah[mt][2], ah[mt][3], bh0, bh1);
                    mma8(acc[mt][nt], al[mt][0], al[mt][1], al[mt][2], al[mt][3], bh0, bh1);
                    mma8(acc[mt][nt], ah[mt][0], ah[mt][1], ah[mt][2], ah[mt][3], bl0, bl1);
                }
            }
        }
        // ---- epilogue: H = relu(D1) ----
        #pragma unroll
        for (int mt = 0; mt < 4; mt++) {
            int r = R0 + mt*16 + gr;
            #pragma unroll
            for (int nt = 0; nt < 4; nt++) {
                int c = C0 + nt*8 + 2*q;
                Hs[r*HS + c]       = fmaxf(acc[mt][nt][0], 0.0f);
                Hs[r*HS + c + 1]   = fmaxf(acc[mt][nt][1], 0.0f);
                Hs[(r+8)*HS + c]   = fmaxf(acc[mt][nt][2], 0.0f);
                Hs[(r+8)*HS + c+1] = fmaxf(acc[mt][nt][3], 0.0f);
            }
        }
        __syncthreads();

        // ================= GEMM2: D2 = H @ W2 (+b2), 3xtf32 =================
        float a2c[2][4];
        #pragma unroll
        for (int nt = 0; nt < 2; nt++) {
            float bz0 = b2s[nt*8 + 2*q];
            float bz1 = b2s[nt*8 + 2*q + 1];
            a2c[nt][0] = bz0; a2c[nt][1] = bz1; a2c[nt][2] = bz0; a2c[nt][3] = bz1;
        }
        #pragma unroll
        for (int kc = 0; kc < 16; kc++) {
            int r = R2 + gr;
            float v0 = Hs[r*HS     + kc*8 + q];
            float v1 = Hs[(r+8)*HS + kc*8 + q];
            float v2 = Hs[r*HS     + kc*8 + q + 4];
            float v3 = Hs[(r+8)*HS + kc*8 + q + 4];
            uint32_t ah0 = tf32h(v0), ah1 = tf32h(v1), ah2 = tf32h(v2), ah3 = tf32h(v3);
            uint32_t al0 = __float_as_uint(v0 - __uint_as_float(ah0));
            uint32_t al1 = __float_as_uint(v1 - __uint_as_float(ah1));
            uint32_t al2 = __float_as_uint(v2 - __uint_as_float(ah2));
            uint32_t al3 = __float_as_uint(v3 - __uint_as_float(ah3));
            #pragma unroll
            for (int nt = 0; nt < 2; nt++) {
                int n = nt*8 + gr;
                uint32_t bh0 = __float_as_uint(W2hp[n*W2S + kc*8 + q]);
                uint32_t bh1 = __float_as_uint(W2hp[n*W2S + kc*8 + q + 4]);
                uint32_t bl0 = __float_as_uint(W2lp[n*W2S + kc*8 + q]);
                uint32_t bl1 = __float_as_uint(W2lp[n*W2S + kc*8 + q + 4]);
                mma8(a2c[nt], ah0, ah1, ah2, ah3, bh0, bh1);
                mma8(a2c[nt], al0, al1, al2, al3, bh0, bh1);
                mma8(a2c[nt], ah0, ah1, ah2, ah3, bl0, bl1);
            }
        }

        // ---- output: s + delta (channel 0 snapshot-restored) ----
        {
            int px0  = R2 + gr;
            int pix0 = y*Wn + x0 + px0;
            #pragma unroll
            for (int nt = 0; nt < 2; nt++) {
                #pragma unroll
                for (int jj = 0; jj < 4; jj++) {
                    int c   = nt*8 + 2*q + (jj & 1);
                    int px  = px0  + ((jj >= 2) ? 8 : 0);
                    int pix = pix0 + ((jj >= 2) ? 8 : 0);
                    float center = rows[(c*3 + 1)*RS + 1 + px];
                    float vout = (c == 0) ? center : (center + a2c[nt][jj]);
                    dst[c*HWn + pix] = vout;
                }
            }
        }
    }
}

extern "C" void kernel_launch(void* const* d_in, const int* in_sizes, int n_in,
                              void* d_out, int out_size)
{
    const float* state = (const float*)d_in[0];
    const float* W1    = (const float*)d_in[1];
    const float* b1    = (const float*)d_in[2];
    const float* W2    = (const float*)d_in[3];
    const float* b2    = (const float*)d_in[4];
    float* out = (float*)d_out;

    cudaFuncSetAttribute(slime_step_mma,
                         cudaFuncAttributeMaxDynamicSharedMemorySize,
                         SMEM_FLOATS * (int)sizeof(float));

    float *bufA, *bufB;
    cudaGetSymbolAddress((void**)&bufA, g_bufA);
    cudaGetSymbolAddress((void**)&bufB, g_bufB);

    w_setup<<<1, 256>>>(W1, W2);

    const float* cur = state;
    for (int s = 0; s < NSTEPS; s++) {
        float* dstp = (s == NSTEPS-1) ? out : ((s & 1) ? bufB : bufA);
        slime_step_mma<<<GRIDX, NTHREADS, SMEM_FLOATS*sizeof(float)>>>(cur, dstp, b1, b2);
        cur = dstp;
    }
}